// round 1
// baseline (speedup 1.0000x reference)
#include <cuda_runtime.h>
#include <cstdint>
#include <math.h>

// Problem constants (fixed by the dataset)
#define NEXPERTS 8
#define TPE      2048     // tokens per expert (16384 / 8)
#define DMODEL   1024
#define DFF      4096

// Tiling
#define BM 128
#define BN 128
#define BK 16
#define STAGES   4
#define NTHREADS 256      // 8 warps: 4 (M) x 2 (N), warp tile 32x64
#define ASTRIDE  20       // BK + 4 pad (floats); 80B rows -> conflict-free ldmatrix
#define BSTRIDE  132      // BN + 4 pad (floats)
#define MI 2              // 32/16 m-tiles per warp
#define NI 8              // 64/8  n-tiles per warp

// Intermediate activations h = gelu(x@w1+b1): 16384 x 4096 fp32 (256 MiB).
// __device__ global scratch (no runtime allocation — allocation guards).
__device__ float g_h[(size_t)NEXPERTS * TPE * DFF];

__device__ __forceinline__ uint32_t smem_u32(const void* p) {
    return (uint32_t)__cvta_generic_to_shared(p);
}
__device__ __forceinline__ void cp_async16(uint32_t dst, const void* src) {
    asm volatile("cp.async.cg.shared.global [%0], [%1], 16;\n" ::"r"(dst), "l"(src));
}
// IMPORTANT: explicit round-to-nearest tf32 conversion. Feeding raw fp32 bits
// to the tf32 MMA truncates the mantissa -> coherent -2^-11 bias across K,
// which would exceed the 1e-3 rel-err budget.
__device__ __forceinline__ uint32_t f2tf32(float f) {
    uint32_t r;
    asm("cvt.rna.tf32.f32 %0, %1;\n" : "=r"(r) : "f"(f));
    return r;
}
__device__ __forceinline__ void ldmatrix_x4(uint32_t r[4], uint32_t addr) {
    asm volatile("ldmatrix.sync.aligned.m8n8.x4.shared.b16 {%0,%1,%2,%3}, [%4];\n"
                 : "=r"(r[0]), "=r"(r[1]), "=r"(r[2]), "=r"(r[3])
                 : "r"(addr));
}
__device__ __forceinline__ void mma_tf32(float c[4], const uint32_t a[4],
                                         uint32_t b0, uint32_t b1) {
    asm volatile(
        "mma.sync.aligned.m16n8k8.row.col.f32.tf32.tf32.f32 "
        "{%0,%1,%2,%3}, {%4,%5,%6,%7}, {%8,%9}, {%0,%1,%2,%3};\n"
        : "+f"(c[0]), "+f"(c[1]), "+f"(c[2]), "+f"(c[3])
        : "r"(a[0]), "r"(a[1]), "r"(a[2]), "r"(a[3]), "r"(b0), "r"(b1));
}
// jax.nn.gelu default is approximate=True (tanh form)
__device__ __forceinline__ float gelu_tanh(float x) {
    float x3 = x * x * x;
    float t  = tanhf(0.7978845608028654f * (x + 0.044715f * x3));
    return 0.5f * x * (1.0f + t);
}

// Grouped GEMM: C[e] = act(A[e] (TPE x K) @ B[e] (K x N) + bias[e]).
// A rows are contiguous per expert (lda = K), B is row-major K x N (ldb = N).
template <bool GELU>
__global__ void __launch_bounds__(NTHREADS, 2)
moe_gemm(const float* __restrict__ Ag, const float* __restrict__ Bg,
         const float* __restrict__ biasg, float* __restrict__ Cg,
         int K, int N)
{
    extern __shared__ float smem[];
    const int e  = blockIdx.z, by = blockIdx.y, bx = blockIdx.x;
    const int tid = threadIdx.x, lane = tid & 31, warp = tid >> 5;
    const int wm = warp & 3;   // warp row (M), 0..3
    const int wn = warp >> 2;  // warp col (N), 0..1

    const float* A    = Ag    + (size_t)(e * TPE + by * BM) * K;
    const float* B    = Bg    + (size_t)e * K * N + (size_t)bx * BN;
    const float* bias = biasg + (size_t)e * N     + (size_t)bx * BN;
    float*       C    = Cg    + (size_t)(e * TPE + by * BM) * N + (size_t)bx * BN;

    float* As_all = smem;                                  // STAGES * BM * ASTRIDE
    float* Bs_all = smem + STAGES * (BM * ASTRIDE);        // STAGES * BK * BSTRIDE

    // cp.async coordinates: A tile = 128x16 (512 x 16B chunks, 2/thread),
    // B tile = 16x128 (512 x 16B chunks, 2/thread). All shapes divide evenly.
    const int a_r = tid >> 2, a_c = (tid & 3) * 4;
    const int b_r = tid >> 5, b_c = (tid & 31) * 4;

    float acc[MI][NI][4];
#pragma unroll
    for (int mi = 0; mi < MI; mi++)
#pragma unroll
        for (int ni = 0; ni < NI; ni++)
#pragma unroll
            for (int i = 0; i < 4; i++) acc[mi][ni][i] = 0.f;

    const int KT = K / BK;

    auto load_stage = [&](int kt, int s) {
        const float* Ak = A + kt * BK;
        const float* Bk = B + (size_t)kt * BK * N;
        float* As = As_all + s * (BM * ASTRIDE);
        float* Bs = Bs_all + s * (BK * BSTRIDE);
        cp_async16(smem_u32(As + a_r * ASTRIDE + a_c),        Ak + (size_t)a_r * K + a_c);
        cp_async16(smem_u32(As + (a_r + 64) * ASTRIDE + a_c), Ak + (size_t)(a_r + 64) * K + a_c);
        cp_async16(smem_u32(Bs + b_r * BSTRIDE + b_c),        Bk + (size_t)b_r * N + b_c);
        cp_async16(smem_u32(Bs + (b_r + 8) * BSTRIDE + b_c),  Bk + (size_t)(b_r + 8) * N + b_c);
    };

#pragma unroll
    for (int s = 0; s < STAGES - 1; s++) {
        load_stage(s, s);
        asm volatile("cp.async.commit_group;\n");
    }

    for (int kt = 0; kt < KT; kt++) {
        asm volatile("cp.async.wait_group %0;\n" ::"n"(STAGES - 2));
        __syncthreads();

        int kn = kt + STAGES - 1;
        if (kn < KT) load_stage(kn, kn % STAGES);
        asm volatile("cp.async.commit_group;\n");

        const float* As = As_all + (kt % STAGES) * (BM * ASTRIDE);
        const float* Bs = Bs_all + (kt % STAGES) * (BK * BSTRIDE);

#pragma unroll
        for (int ks = 0; ks < BK / 8; ks++) {
            // A fragments via ldmatrix.x4 (b16 view of tf32 tile):
            // lanes 0-7 -> rows 0-7 (cols 0-3), 8-15 -> rows 8-15,
            // 16-23 -> rows 0-7 (cols 4-7), 24-31 -> rows 8-15 (cols 4-7).
            uint32_t a[MI][4];
#pragma unroll
            for (int mi = 0; mi < MI; mi++) {
                int row = wm * 32 + mi * 16 + (lane & 15);
                uint32_t addr = smem_u32(As + row * ASTRIDE + ks * 8 + (lane >> 4) * 4);
                ldmatrix_x4(a[mi], addr);
#pragma unroll
                for (int i = 0; i < 4; i++) a[mi][i] = f2tf32(__uint_as_float(a[mi][i]));
            }
            // B fragments: b0 = B[k0 + lane%4][n], b1 = B[k0 + lane%4 + 4][n]
            const float* p0 = Bs + (ks * 8 + (lane & 3)) * BSTRIDE + wn * 64 + (lane >> 2);
            const float* p1 = p0 + 4 * BSTRIDE;
#pragma unroll
            for (int ni = 0; ni < NI; ni++) {
                uint32_t b0 = f2tf32(p0[ni * 8]);
                uint32_t b1 = f2tf32(p1[ni * 8]);
#pragma unroll
                for (int mi = 0; mi < MI; mi++)
                    mma_tf32(acc[mi][ni], a[mi], b0, b1);
            }
        }
    }

    // Epilogue: bias (+GELU), fp32 stores (float2 per accumulator row pair)
#pragma unroll
    for (int mi = 0; mi < MI; mi++) {
        int row = wm * 32 + mi * 16 + (lane >> 2);
#pragma unroll
        for (int ni = 0; ni < NI; ni++) {
            int col = wn * 64 + ni * 8 + (lane & 3) * 2;
            float bz0 = bias[col], bz1 = bias[col + 1];
            float v00 = acc[mi][ni][0] + bz0, v01 = acc[mi][ni][1] + bz1;
            float v10 = acc[mi][ni][2] + bz0, v11 = acc[mi][ni][3] + bz1;
            if (GELU) {
                v00 = gelu_tanh(v00); v01 = gelu_tanh(v01);
                v10 = gelu_tanh(v10); v11 = gelu_tanh(v11);
            }
            *(float2*)(C + (size_t)row * N + col)       = make_float2(v00, v01);
            *(float2*)(C + (size_t)(row + 8) * N + col) = make_float2(v10, v11);
        }
    }
}

extern "C" void kernel_launch(void* const* d_in, const int* in_sizes, int n_in,
                              void* d_out, int out_size)
{
    const float* x  = (const float*)d_in[0];
    // d_in[1] = expert_size (uniform T/E by construction; unused)
    const float* w1 = (const float*)d_in[2];
    const float* b1 = (const float*)d_in[3];
    const float* w2 = (const float*)d_in[4];
    const float* b2 = (const float*)d_in[5];
    float* y = (float*)d_out;

    float* h = nullptr;
    cudaGetSymbolAddress((void**)&h, g_h);

    const int smem_bytes = STAGES * (BM * ASTRIDE + BK * BSTRIDE) * (int)sizeof(float);
    cudaFuncSetAttribute((const void*)moe_gemm<true>,
                         cudaFuncAttributeMaxDynamicSharedMemorySize, smem_bytes);
    cudaFuncSetAttribute((const void*)moe_gemm<false>,
                         cudaFuncAttributeMaxDynamicSharedMemorySize, smem_bytes);

    dim3 blk(NTHREADS);
    // GEMM1: h = gelu(x @ w1 + b1)   [per expert: 2048x1024 @ 1024x4096]
    dim3 g1(DFF / BN, TPE / BM, NEXPERTS);
    moe_gemm<true><<<g1, blk, smem_bytes>>>(x, w1, b1, h, DMODEL, DFF);
    // GEMM2: y = h @ w2 + b2         [per expert: 2048x4096 @ 4096x1024]
    dim3 g2(DMODEL / BN, TPE / BM, NEXPERTS);
    moe_gemm<false><<<g2, blk, smem_bytes>>>(h, w2, b2, y, DFF, DMODEL);
}

// round 3
// speedup vs baseline: 1.0748x; 1.0748x over previous
#include <cuda_runtime.h>
#include <cstdint>
#include <math.h>

// ---------------- problem constants ----------------
#define NE      8
#define TPE     2048
#define DMODEL  1024
#define DFF     4096

// ---------------- tiling ----------------
#define BM      128
#define BN      128
#define BK      16
#define STAGES  4
#define NT      256      // 8 warps: 4 (M) x 2 (N); warp tile 32 x 64
#define STRIDE  20       // smem row pitch in floats (16 + 4 pad) -> conflict-free LDSM
#define MI      2
#define NI      8

// ---------------- device scratch (no runtime allocation) ----------------
__device__ float g_x  [(size_t)NE * TPE * DMODEL];   // tf32-rounded x
__device__ float g_h  [(size_t)NE * TPE * DFF];      // gelu(x@w1+b1), tf32-rounded
__device__ float g_w1t[(size_t)NE * DMODEL * DFF];   // w1^T per expert: [F, D], rounded
__device__ float g_w2t[(size_t)NE * DMODEL * DFF];   // w2^T per expert: [D, F], rounded

// ---------------- helpers ----------------
__device__ __forceinline__ uint32_t smem_u32(const void* p) {
    return (uint32_t)__cvta_generic_to_shared(p);
}
__device__ __forceinline__ void cp_async16(uint32_t dst, const void* src) {
    asm volatile("cp.async.cg.shared.global [%0], [%1], 16;\n" ::"r"(dst), "l"(src));
}
__device__ __forceinline__ float tf32r(float f) {   // round-to-nearest tf32, kept as f32
    uint32_t u;
    asm("cvt.rna.tf32.f32 %0, %1;\n" : "=r"(u) : "f"(f));
    return __uint_as_float(u);
}
__device__ __forceinline__ void ldmatrix_x4(uint32_t r[4], uint32_t addr) {
    asm volatile("ldmatrix.sync.aligned.m8n8.x4.shared.b16 {%0,%1,%2,%3}, [%4];\n"
                 : "=r"(r[0]), "=r"(r[1]), "=r"(r[2]), "=r"(r[3])
                 : "r"(addr));
}
__device__ __forceinline__ void mma_tf32(float c[4], const uint32_t a[4],
                                         uint32_t b0, uint32_t b1) {
    asm volatile(
        "mma.sync.aligned.m16n8k8.row.col.f32.tf32.tf32.f32 "
        "{%0,%1,%2,%3}, {%4,%5,%6,%7}, {%8,%9}, {%0,%1,%2,%3};\n"
        : "+f"(c[0]), "+f"(c[1]), "+f"(c[2]), "+f"(c[3])
        : "r"(a[0]), "r"(a[1]), "r"(a[2]), "r"(a[3]), "r"(b0), "r"(b1));
}
__device__ __forceinline__ float gelu_tanh(float x) {   // jax.nn.gelu (tanh form)
    float x3 = x * x * x;
    float t  = tanhf(0.7978845608028654f * (x + 0.044715f * x3));
    return 0.5f * x * (1.0f + t);
}

// ---------------- pre-passes ----------------
__global__ void round_x_k(const float* __restrict__ in, float* __restrict__ out, int n4) {
    int i = blockIdx.x * blockDim.x + threadIdx.x;
    if (i < n4) {
        float4 v = ((const float4*)in)[i];
        v.x = tf32r(v.x); v.y = tf32r(v.y); v.z = tf32r(v.z); v.w = tf32r(v.w);
        ((float4*)out)[i] = v;
    }
}
// per-expert transpose: in[e] (R x C) -> out[e] (C x R), tf32-rounded
__global__ void transpose_round_k(const float* __restrict__ in, float* __restrict__ out,
                                  int R, int C) {
    __shared__ float t[32][33];
    const float* ip = in  + (size_t)blockIdx.z * R * C;
    float*       op = out + (size_t)blockIdx.z * R * C;
    int r0 = blockIdx.y << 5, c0 = blockIdx.x << 5;
    int x = threadIdx.x & 31, y = threadIdx.x >> 5;
#pragma unroll
    for (int j = 0; j < 4; j++)
        t[y + j * 8][x] = ip[(size_t)(r0 + y + j * 8) * C + c0 + x];
    __syncthreads();
#pragma unroll
    for (int j = 0; j < 4; j++)
        op[(size_t)(c0 + y + j * 8) * R + r0 + x] = tf32r(t[x][y + j * 8]);
}

// ---------------- grouped GEMM: C = act(A @ Bt^T + bias) ----------------
// A:  [E*TPE, K] row-major (K-major), pre-rounded to tf32.
// Bt: per expert [N, K] (K-major), pre-transposed + rounded.
// All operands tf32-clean -> no cvt in the mainloop; A and B frags via ldmatrix.
template <bool GELU>
__global__ void __launch_bounds__(NT, 2)
moe_gemm(const float* __restrict__ Ag, const float* __restrict__ Btg,
         const float* __restrict__ biasg, float* __restrict__ Cg,
         int K, int N)
{
    extern __shared__ float smem[];
    const int e = blockIdx.z, by = blockIdx.y, bx = blockIdx.x;
    const int tid = threadIdx.x, lane = tid & 31, warp = tid >> 5;
    const int wm = warp & 3;    // warp row (M)
    const int wn = warp >> 2;   // warp col (N)

    const float* A    = Ag   + (size_t)(e * TPE + by * BM) * K;
    const float* Bt   = Btg  + (size_t)e * K * N + (size_t)(bx * BN) * K;
    const float* bias = biasg + (size_t)e * N + (size_t)bx * BN;
    float*       C    = Cg   + (size_t)(e * TPE + by * BM) * N + (size_t)bx * BN;

    float* As_all = smem;                              // STAGES * BM * STRIDE
    float* Bs_all = smem + STAGES * (BM * STRIDE);     // STAGES * BN * STRIDE

    // cp.async: A tile 128x16 (512 chunks of 16B), B tile 128x16 (512 chunks).
    // 2 chunks each per thread; 2 threads per row.
    const int ld_r = tid >> 1, ld_c = (tid & 1) * 8;

    float acc[MI][NI][4];
#pragma unroll
    for (int mi = 0; mi < MI; mi++)
#pragma unroll
        for (int ni = 0; ni < NI; ni++)
#pragma unroll
            for (int i = 0; i < 4; i++) acc[mi][ni][i] = 0.f;

    const int KT = K / BK;

    auto load_stage = [&](int kt, int s) {
        const float* Ak  = A  + kt * BK;
        const float* Btk = Bt + kt * BK;
        float* As = As_all + s * (BM * STRIDE);
        float* Bs = Bs_all + s * (BN * STRIDE);
        cp_async16(smem_u32(As + ld_r * STRIDE + ld_c),     Ak  + (size_t)ld_r * K + ld_c);
        cp_async16(smem_u32(As + ld_r * STRIDE + ld_c + 4), Ak  + (size_t)ld_r * K + ld_c + 4);
        cp_async16(smem_u32(Bs + ld_r * STRIDE + ld_c),     Btk + (size_t)ld_r * K + ld_c);
        cp_async16(smem_u32(Bs + ld_r * STRIDE + ld_c + 4), Btk + (size_t)ld_r * K + ld_c + 4);
    };

#pragma unroll
    for (int s = 0; s < STAGES - 1; s++) {
        load_stage(s, s);
        asm volatile("cp.async.commit_group;\n");
    }

    for (int kt = 0; kt < KT; kt++) {
        asm volatile("cp.async.wait_group %0;\n" ::"n"(STAGES - 2));
        __syncthreads();

        int kn = kt + STAGES - 1;
        if (kn < KT) load_stage(kn, kn % STAGES);
        asm volatile("cp.async.commit_group;\n");

        const float* As = As_all + (kt % STAGES) * (BM * STRIDE);
        const float* Bs = Bs_all + (kt % STAGES) * (BN * STRIDE);

#pragma unroll
        for (int ks = 0; ks < BK / 8; ks++) {
            // ---- A fragments (ldmatrix.x4; b16 view of the tf32 tile) ----
            uint32_t a[MI][4];
#pragma unroll
            for (int mi = 0; mi < MI; mi++) {
                int row = wm * 32 + mi * 16 + (lane & 15);
                ldmatrix_x4(a[mi], smem_u32(As + row * STRIDE + ks * 8 + (lane >> 4) * 4));
            }
            // ---- B fragments: n-major smem, one ldmatrix.x4 per 2 n-groups ----
            // matrices: 0 -> (n0..n0+7, k lo), 1 -> (k hi), 2 -> (n0+8.., k lo), 3 -> (k hi)
            uint32_t b[NI][2];
#pragma unroll
            for (int nj = 0; nj < NI / 2; nj++) {
                int row = wn * 64 + nj * 16 + ((lane >> 4) & 1) * 8 + (lane & 7);
                uint32_t r[4];
                ldmatrix_x4(r, smem_u32(Bs + row * STRIDE + ks * 8 + ((lane >> 3) & 1) * 4));
                b[2 * nj][0] = r[0]; b[2 * nj][1] = r[1];
                b[2 * nj + 1][0] = r[2]; b[2 * nj + 1][1] = r[3];
            }
#pragma unroll
            for (int ni = 0; ni < NI; ni++)
#pragma unroll
                for (int mi = 0; mi < MI; mi++)
                    mma_tf32(acc[mi][ni], a[mi], b[ni][0], b[ni][1]);
        }
    }

    // ---------------- epilogue: bias (+GELU, tf32 round) ----------------
#pragma unroll
    for (int mi = 0; mi < MI; mi++) {
        int row = wm * 32 + mi * 16 + (lane >> 2);
#pragma unroll
        for (int ni = 0; ni < NI; ni++) {
            int col = wn * 64 + ni * 8 + (lane & 3) * 2;
            float bz0 = bias[col], bz1 = bias[col + 1];
            float v00 = acc[mi][ni][0] + bz0, v01 = acc[mi][ni][1] + bz1;
            float v10 = acc[mi][ni][2] + bz0, v11 = acc[mi][ni][3] + bz1;
            if (GELU) {   // h feeds GEMM2's A: round to tf32 here
                v00 = tf32r(gelu_tanh(v00)); v01 = tf32r(gelu_tanh(v01));
                v10 = tf32r(gelu_tanh(v10)); v11 = tf32r(gelu_tanh(v11));
            }
            *(float2*)(C + (size_t)row * N + col)       = make_float2(v00, v01);
            *(float2*)(C + (size_t)(row + 8) * N + col) = make_float2(v10, v11);
        }
    }
}

// ---------------- launch ----------------
extern "C" void kernel_launch(void* const* d_in, const int* in_sizes, int n_in,
                              void* d_out, int out_size)
{
    const float* x  = (const float*)d_in[0];
    const float* w1 = (const float*)d_in[2];
    const float* b1 = (const float*)d_in[3];
    const float* w2 = (const float*)d_in[4];
    const float* b2 = (const float*)d_in[5];
    float* y = (float*)d_out;

    float *xr, *h, *w1t, *w2t;
    cudaGetSymbolAddress((void**)&xr,  g_x);
    cudaGetSymbolAddress((void**)&h,   g_h);
    cudaGetSymbolAddress((void**)&w1t, g_w1t);
    cudaGetSymbolAddress((void**)&w2t, g_w2t);

    const int smem_bytes = STAGES * (BM * STRIDE + BN * STRIDE) * (int)sizeof(float);
    cudaFuncSetAttribute((const void*)moe_gemm<true>,
                         cudaFuncAttributeMaxDynamicSharedMemorySize, smem_bytes);
    cudaFuncSetAttribute((const void*)moe_gemm<false>,
                         cudaFuncAttributeMaxDynamicSharedMemorySize, smem_bytes);

    // pre-passes: round x; transpose + round weights to K-major [N, K]
    {
        int n4 = NE * TPE * DMODEL / 4;
        round_x_k<<<(n4 + 255) / 256, 256>>>(x, xr, n4);
        dim3 t1(DFF / 32, DMODEL / 32, NE);     // w1 [D,F] -> w1t [F,D]
        transpose_round_k<<<t1, 256>>>(w1, w1t, DMODEL, DFF);
        dim3 t2(DMODEL / 32, DFF / 32, NE);     // w2 [F,D] -> w2t [D,F]
        transpose_round_k<<<t2, 256>>>(w2, w2t, DFF, DMODEL);
    }

    dim3 blk(NT);
    // GEMM1: h = gelu(x @ w1 + b1)   per expert 2048x1024 @ 1024x4096
    dim3 g1(DFF / BN, TPE / BM, NE);
    moe_gemm<true><<<g1, blk, smem_bytes>>>(xr, w1t, b1, h, DMODEL, DFF);
    // GEMM2: y = h @ w2 + b2         per expert 2048x4096 @ 4096x1024
    dim3 g2(DMODEL / BN, TPE / BM, NE);
    moe_gemm<false><<<g2, blk, smem_bytes>>>(h, w2t, b2, y, DFF, DMODEL);
}

// round 4
// speedup vs baseline: 1.2512x; 1.1641x over previous
#include <cuda_runtime.h>
#include <cstdint>
#include <math.h>

// ---------------- problem constants ----------------
#define NE      8
#define TPE     2048
#define DMODEL  1024
#define DFF     4096

// ---------------- tiling ----------------
#define BM      128
#define BN      128
#define BK      32
#define STAGES  3
#define NT      256      // 8 warps: 4 (M) x 2 (N); warp tile 32 x 64
#define STRIDE  36       // smem row pitch in floats (32 + 4 pad) -> conflict-free LDSM/STS
#define MI      2
#define NI      8

// ---------------- device scratch (no runtime allocation) ----------------
__device__ float g_x  [(size_t)NE * TPE * DMODEL];   // tf32-rounded x
__device__ float g_h  [(size_t)NE * TPE * DFF];      // gelu(x@w1+b1), tf32-rounded
__device__ float g_w1t[(size_t)NE * DMODEL * DFF];   // w1^T per expert: [F, D], rounded
__device__ float g_w2t[(size_t)NE * DMODEL * DFF];   // w2^T per expert: [D, F], rounded

// ---------------- helpers ----------------
__device__ __forceinline__ uint32_t smem_u32(const void* p) {
    return (uint32_t)__cvta_generic_to_shared(p);
}
__device__ __forceinline__ void cp_async16(uint32_t dst, const void* src) {
    asm volatile("cp.async.cg.shared.global [%0], [%1], 16;\n" ::"r"(dst), "l"(src));
}
__device__ __forceinline__ float tf32r(float f) {   // round-to-nearest tf32, kept as f32
    uint32_t u;
    asm("cvt.rna.tf32.f32 %0, %1;\n" : "=r"(u) : "f"(f));
    return __uint_as_float(u);
}
__device__ __forceinline__ void ldmatrix_x4(uint32_t r[4], uint32_t addr) {
    asm volatile("ldmatrix.sync.aligned.m8n8.x4.shared.b16 {%0,%1,%2,%3}, [%4];\n"
                 : "=r"(r[0]), "=r"(r[1]), "=r"(r[2]), "=r"(r[3])
                 : "r"(addr));
}
__device__ __forceinline__ void mma_tf32(float c[4], const uint32_t a[4],
                                         uint32_t b0, uint32_t b1) {
    asm volatile(
        "mma.sync.aligned.m16n8k8.row.col.f32.tf32.tf32.f32 "
        "{%0,%1,%2,%3}, {%4,%5,%6,%7}, {%8,%9}, {%0,%1,%2,%3};\n"
        : "+f"(c[0]), "+f"(c[1]), "+f"(c[2]), "+f"(c[3])
        : "r"(a[0]), "r"(a[1]), "r"(a[2]), "r"(a[3]), "r"(b0), "r"(b1));
}
__device__ __forceinline__ float gelu_tanh(float x) {   // jax.nn.gelu (tanh form)
    float x3 = x * x * x;
    float t  = tanhf(0.7978845608028654f * (x + 0.044715f * x3));
    return 0.5f * x * (1.0f + t);
}

// ---------------- pre-passes ----------------
__global__ void round_x_k(const float* __restrict__ in, float* __restrict__ out, int n4) {
    int i = blockIdx.x * blockDim.x + threadIdx.x;
    if (i < n4) {
        float4 v = ((const float4*)in)[i];
        v.x = tf32r(v.x); v.y = tf32r(v.y); v.z = tf32r(v.z); v.w = tf32r(v.w);
        ((float4*)out)[i] = v;
    }
}
// per-expert transpose: in[e] (R x C) -> out[e] (C x R), tf32-rounded
__global__ void transpose_round_k(const float* __restrict__ in, float* __restrict__ out,
                                  int R, int C) {
    __shared__ float t[32][33];
    const float* ip = in  + (size_t)blockIdx.z * R * C;
    float*       op = out + (size_t)blockIdx.z * R * C;
    int r0 = blockIdx.y << 5, c0 = blockIdx.x << 5;
    int x = threadIdx.x & 31, y = threadIdx.x >> 5;
#pragma unroll
    for (int j = 0; j < 4; j++)
        t[y + j * 8][x] = ip[(size_t)(r0 + y + j * 8) * C + c0 + x];
    __syncthreads();
#pragma unroll
    for (int j = 0; j < 4; j++)
        op[(size_t)(c0 + y + j * 8) * R + r0 + x] = tf32r(t[x][y + j * 8]);
}

// ---------------- grouped GEMM: C = act(A @ Bt^T + bias) ----------------
// A:  [E*TPE, K] row-major (K-major), tf32-pre-rounded.
// Bt: per expert [N, K] (K-major), pre-transposed + rounded.
template <bool GELU>
__global__ void __launch_bounds__(NT, 2)
moe_gemm(const float* __restrict__ Ag, const float* __restrict__ Btg,
         const float* __restrict__ biasg, float* __restrict__ Cg,
         int K, int N)
{
    extern __shared__ float smem[];
    const int e = blockIdx.z, by = blockIdx.y, bx = blockIdx.x;
    const int tid = threadIdx.x, lane = tid & 31, warp = tid >> 5;
    const int wm = warp & 3;    // warp row (M)
    const int wn = warp >> 2;   // warp col (N)

    const float* A    = Ag    + (size_t)(e * TPE + by * BM) * K;
    const float* Bt   = Btg   + (size_t)e * K * N + (size_t)(bx * BN) * K;
    const float* bias = biasg + (size_t)e * N + (size_t)bx * BN;
    float*       C    = Cg    + (size_t)(e * TPE + by * BM) * N + (size_t)bx * BN;

    float* As_all = smem;                              // STAGES * BM * STRIDE
    float* Bs_all = smem + STAGES * (BM * STRIDE);     // STAGES * BN * STRIDE

    // cp.async: each tile 128 rows x 32 floats = 1024 x 16B chunks; 256 threads,
    // 4 threads per row (2 chunks each), rows r and r+64.
    const int ld_r = tid >> 2, ld_c = (tid & 3) * 8;

    float acc[MI][NI][4];
#pragma unroll
    for (int mi = 0; mi < MI; mi++)
#pragma unroll
        for (int ni = 0; ni < NI; ni++)
#pragma unroll
            for (int i = 0; i < 4; i++) acc[mi][ni][i] = 0.f;

    const int KT = K / BK;

    auto load_stage = [&](int kt, int s) {
        const float* Ak  = A  + kt * BK;
        const float* Btk = Bt + kt * BK;
        float* As = As_all + s * (BM * STRIDE);
        float* Bs = Bs_all + s * (BN * STRIDE);
#pragma unroll
        for (int half = 0; half < 2; half++) {
            int r = ld_r + half * 64;
            cp_async16(smem_u32(As + r * STRIDE + ld_c),     Ak  + (size_t)r * K + ld_c);
            cp_async16(smem_u32(As + r * STRIDE + ld_c + 4), Ak  + (size_t)r * K + ld_c + 4);
            cp_async16(smem_u32(Bs + r * STRIDE + ld_c),     Btk + (size_t)r * K + ld_c);
            cp_async16(smem_u32(Bs + r * STRIDE + ld_c + 4), Btk + (size_t)r * K + ld_c + 4);
        }
    };

#pragma unroll
    for (int s = 0; s < STAGES - 1; s++) {
        load_stage(s, s);
        asm volatile("cp.async.commit_group;\n");
    }

    for (int kt = 0; kt < KT; kt++) {
        asm volatile("cp.async.wait_group %0;\n" ::"n"(STAGES - 2));
        __syncthreads();

        int kn = kt + STAGES - 1;
        if (kn < KT) load_stage(kn, kn % STAGES);
        asm volatile("cp.async.commit_group;\n");

        const float* As = As_all + (kt % STAGES) * (BM * STRIDE);
        const float* Bs = Bs_all + (kt % STAGES) * (BN * STRIDE);

#pragma unroll
        for (int ks = 0; ks < BK / 8; ks++) {
            // ---- A fragments (ldmatrix.x4; b16 view of the tf32 tile) ----
            uint32_t a[MI][4];
#pragma unroll
            for (int mi = 0; mi < MI; mi++) {
                int row = wm * 32 + mi * 16 + (lane & 15);
                ldmatrix_x4(a[mi], smem_u32(As + row * STRIDE + ks * 8 + (lane >> 4) * 4));
            }
            // ---- interleave: one B ldmatrix.x4 (2 n-groups), then its 4 MMAs ----
#pragma unroll
            for (int nj = 0; nj < NI / 2; nj++) {
                int row = wn * 64 + nj * 16 + ((lane >> 4) & 1) * 8 + (lane & 7);
                uint32_t r[4];
                ldmatrix_x4(r, smem_u32(Bs + row * STRIDE + ks * 8 + ((lane >> 3) & 1) * 4));
#pragma unroll
                for (int mi = 0; mi < MI; mi++) {
                    mma_tf32(acc[mi][2 * nj],     a[mi], r[0], r[1]);
                    mma_tf32(acc[mi][2 * nj + 1], a[mi], r[2], r[3]);
                }
            }
        }
    }

    // ---------------- epilogue: bias (+GELU, tf32 round) ----------------
#pragma unroll
    for (int mi = 0; mi < MI; mi++) {
        int row = wm * 32 + mi * 16 + (lane >> 2);
#pragma unroll
        for (int ni = 0; ni < NI; ni++) {
            int col = wn * 64 + ni * 8 + (lane & 3) * 2;
            float bz0 = bias[col], bz1 = bias[col + 1];
            float v00 = acc[mi][ni][0] + bz0, v01 = acc[mi][ni][1] + bz1;
            float v10 = acc[mi][ni][2] + bz0, v11 = acc[mi][ni][3] + bz1;
            if (GELU) {   // h feeds GEMM2's A: round to tf32 here
                v00 = tf32r(gelu_tanh(v00)); v01 = tf32r(gelu_tanh(v01));
                v10 = tf32r(gelu_tanh(v10)); v11 = tf32r(gelu_tanh(v11));
            }
            *(float2*)(C + (size_t)row * N + col)       = make_float2(v00, v01);
            *(float2*)(C + (size_t)(row + 8) * N + col) = make_float2(v10, v11);
        }
    }
}

// ---------------- launch ----------------
extern "C" void kernel_launch(void* const* d_in, const int* in_sizes, int n_in,
                              void* d_out, int out_size)
{
    const float* x  = (const float*)d_in[0];
    const float* w1 = (const float*)d_in[2];
    const float* b1 = (const float*)d_in[3];
    const float* w2 = (const float*)d_in[4];
    const float* b2 = (const float*)d_in[5];
    float* y = (float*)d_out;

    float *xr, *h, *w1t, *w2t;
    cudaGetSymbolAddress((void**)&xr,  g_x);
    cudaGetSymbolAddress((void**)&h,   g_h);
    cudaGetSymbolAddress((void**)&w1t, g_w1t);
    cudaGetSymbolAddress((void**)&w2t, g_w2t);

    const int smem_bytes = STAGES * (BM * STRIDE + BN * STRIDE) * (int)sizeof(float);
    cudaFuncSetAttribute((const void*)moe_gemm<true>,
                         cudaFuncAttributeMaxDynamicSharedMemorySize, smem_bytes);
    cudaFuncSetAttribute((const void*)moe_gemm<false>,
                         cudaFuncAttributeMaxDynamicSharedMemorySize, smem_bytes);

    // pre-passes: round x; transpose + round weights to K-major [N, K]
    {
        int n4 = NE * TPE * DMODEL / 4;
        round_x_k<<<(n4 + 255) / 256, 256>>>(x, xr, n4);
        dim3 t1(DFF / 32, DMODEL / 32, NE);     // w1 [D,F] -> w1t [F,D]
        transpose_round_k<<<t1, 256>>>(w1, w1t, DMODEL, DFF);
        dim3 t2(DMODEL / 32, DFF / 32, NE);     // w2 [F,D] -> w2t [D,F]
        transpose_round_k<<<t2, 256>>>(w2, w2t, DFF, DMODEL);
    }

    dim3 blk(NT);
    // GEMM1: h = gelu(x @ w1 + b1)   per expert 2048x1024 @ 1024x4096
    dim3 g1(DFF / BN, TPE / BM, NE);
    moe_gemm<true><<<g1, blk, smem_bytes>>>(xr, w1t, b1, h, DMODEL, DFF);
    // GEMM2: y = h @ w2 + b2         per expert 2048x4096 @ 4096x1024
    dim3 g2(DMODEL / BN, TPE / BM, NE);
    moe_gemm<false><<<g2, blk, smem_bytes>>>(h, w2t, b2, y, DFF, DMODEL);
}